// round 4
// baseline (speedup 1.0000x reference)
#include <cuda_runtime.h>
#include <cuda_fp16.h>
#include <math.h>
#include <stdint.h>

// ---------------- problem constants ----------------
#define BB 4
#define NN 4096
#define DD 1024
#define HH 16
#define HD 64
#define MTOT (BB*NN)          // 16384
#define N3D (3*DD)            // 3072
#define NSCALES 11

#define C0 0.4829629131445341f
#define C1 0.8365163037378079f
#define C2 0.2241438680420134f
#define C3 (-0.1294095225512604f)

// ---------------- scratch (device globals; allocation-free) ----------------
__device__ __half g_xh    [(size_t)MTOT * DD];      // 32 MB
__device__ __half g_qh    [(size_t)MTOT * DD];      // 32 MB
__device__ float  g_kv    [(size_t)MTOT * 2*DD];    // 128 MB (k | v)
__device__ float  g_gate  [(size_t)MTOT * DD];      // 64 MB
__device__ float  g_field [(size_t)BB*HH*HD*NN];    // [bh][d][n] 64 MB
__device__ float  g_acc   [(size_t)BB*HH*HD*NN];    // 64 MB
__device__ __half g_preh  [(size_t)MTOT * DD];      // 32 MB
__device__ __half g_wqkvT [(size_t)N3D * DD];       // 6 MB  [n][k]
__device__ __half g_wgateT[(size_t)DD * DD];
__device__ __half g_woutT [(size_t)DD * DD];
__device__ float  g_gains [NSCALES*HH];
__device__ float  g_sw    [2];
__device__ float  g_coup  [HH*HH];

// ---------------- helpers ----------------
__device__ __forceinline__ void cpa16(uint32_t s, const void* g) {
    asm volatile("cp.async.cg.shared.global [%0], [%1], 16;\n" :: "r"(s), "l"(g));
}
__device__ __forceinline__ void mma16816(float* d, const uint32_t* a, const uint32_t* b) {
    asm volatile(
        "mma.sync.aligned.m16n8k16.row.col.f32.f16.f16.f32 "
        "{%0,%1,%2,%3}, {%4,%5,%6,%7}, {%8,%9}, {%0,%1,%2,%3};\n"
        : "+f"(d[0]), "+f"(d[1]), "+f"(d[2]), "+f"(d[3])
        : "r"(a[0]), "r"(a[1]), "r"(a[2]), "r"(a[3]), "r"(b[0]), "r"(b[1]));
}

// ---------------- K0: tiny prep ----------------
__global__ void prep_kernel(const float* __restrict__ scale_gain,
                            const float* __restrict__ skip_w,
                            const float* __restrict__ coupling) {
    int t = threadIdx.x;
    if (t < HH) {
        float m = -1e30f;
        for (int j = 0; j < NSCALES; j++) m = fmaxf(m, scale_gain[j*HH + t]);
        float e[NSCALES]; float s = 0.f;
        for (int j = 0; j < NSCALES; j++) { e[j] = expf(scale_gain[j*HH + t] - m); s += e[j]; }
        for (int j = 0; j < NSCALES; j++) g_gains[j*HH + t] = e[j] / s;
        float m2 = -1e30f;
        for (int j = 0; j < HH; j++) m2 = fmaxf(m2, coupling[t*HH + j]);
        float e2[HH]; float s2 = 0.f;
        for (int j = 0; j < HH; j++) { e2[j] = expf(coupling[t*HH + j] - m2); s2 += e2[j]; }
        for (int j = 0; j < HH; j++) g_coup[t*HH + j] = e2[j] / s2;
    }
    if (t < 2) g_sw[t] = 1.f / (1.f + expf(-skip_w[t]));
}

// ---------------- weight transpose to half: Wt[n][k] = (half)W[k][n] --------
__global__ __launch_bounds__(256)
void wtrans_kernel(const float* __restrict__ W, __half* __restrict__ Wt,
                   int K, int Nw) {
    __shared__ float s[32][33];
    int n0 = blockIdx.x * 32, k0 = blockIdx.y * 32;
    int tx = threadIdx.x & 31, ty = threadIdx.x >> 5;
    #pragma unroll
    for (int i = 0; i < 32; i += 8)
        s[ty + i][tx] = W[(size_t)(k0 + ty + i) * Nw + n0 + tx];
    __syncthreads();
    #pragma unroll
    for (int i = 0; i < 32; i += 8)
        Wt[(size_t)(n0 + ty + i) * K + k0 + tx] = __float2half_rn(s[tx][ty + i]);
}

// ---------------- x -> half ----------------
__global__ __launch_bounds__(256)
void tohalf_kernel(const float* __restrict__ in, __half* __restrict__ out) {
    size_t i = (size_t)blockIdx.x * 256 + threadIdx.x;
    float4 v = reinterpret_cast<const float4*>(in)[i];
    __half2 h01 = __floats2half2_rn(v.x, v.y);
    __half2 h23 = __floats2half2_rn(v.z, v.w);
    uint2 u = make_uint2(*(uint32_t*)&h01, *(uint32_t*)&h23);
    reinterpret_cast<uint2*>(out)[i] = u;
}

// ---------------- fp16 tensor-core GEMM: C = A[M,K] @ Bt[N,K]^T + bias ------
// BM=BN=128, BK=32, 256 threads, 8 warps (2x4), warp tile 64x32, 3-stage.
#define STRH 40                    // smem row stride in halves (80B): conflict-free
#define OPH  (128*STRH)            // halves per operand per stage
#define STGH (2*OPH)               // halves per stage
#define NSTAGE 3
#define GSMEM (NSTAGE*STGH*2)      // 61440 bytes

// MODE 0: write fp32 C (+ optional sigmoid via ACT). MODE 1: qkv split:
//   col<DD -> half into g_qh ; col>=DD -> fp32 into g_kv (ldc 2048).
template<int ACT, int MODE>
__global__ __launch_bounds__(256)
void mma_gemm(const __half* __restrict__ A,
              const __half* __restrict__ Bt,
              const float* __restrict__ bias,
              float* __restrict__ C, int ldc, int K) {
    extern __shared__ __half smh[];
    const int tid  = threadIdx.x;
    const int lane = tid & 31;
    const int warp = tid >> 5;
    const int row0 = blockIdx.y * 128;
    const int col0 = blockIdx.x * 128;
    const int wr0  = (warp >> 2) * 64;
    const int wc0  = (warp & 3) * 32;
    const int lq   = lane >> 2;
    const int lr   = lane & 3;

    const uint32_t smem_base = (uint32_t)__cvta_generic_to_shared(smh);

    float acc[4][4][4];
    #pragma unroll
    for (int r = 0; r < 4; r++)
        #pragma unroll
        for (int c = 0; c < 4; c++)
            #pragma unroll
            for (int e = 0; e < 4; e++) acc[r][c][e] = 0.f;

    // loader: 512 16B-chunks per operand per stage; 2 chunks/thread each
    const int lrow = tid >> 1;            // 0..127
    const int lkc  = (tid & 1) * 16;      // 0 or 16 (halves); +8 for 2nd chunk

    auto load_tile = [&](int stage, int kt) {
        const __half* Agk = A  + (size_t)(row0 + lrow) * K + kt*32 + lkc;
        const __half* Bgk = Bt + (size_t)(col0 + lrow) * K + kt*32 + lkc;
        uint32_t sa = smem_base + (stage * STGH + lrow * STRH + lkc) * 2;
        uint32_t sb = sa + OPH * 2;
        cpa16(sa,      Agk);
        cpa16(sa + 16, Agk + 8);
        cpa16(sb,      Bgk);
        cpa16(sb + 16, Bgk + 8);
        asm volatile("cp.async.commit_group;\n");
    };

    const int KT = K >> 5;
    load_tile(0, 0);
    load_tile(1, 1);

    for (int kt = 0; kt < KT; kt++) {
        if (kt + 1 < KT) asm volatile("cp.async.wait_group 1;\n");
        else             asm volatile("cp.async.wait_group 0;\n");
        __syncthreads();
        if (kt + 2 < KT) load_tile((kt + 2) % NSTAGE, kt + 2);

        const __half* sA = smh + (kt % NSTAGE) * STGH;
        const __half* sB = sA + OPH;
        #pragma unroll
        for (int kk = 0; kk < 32; kk += 16) {
            uint32_t af[4][4], bf[4][2];
            #pragma unroll
            for (int r = 0; r < 4; r++) {
                const __half* p = sA + (wr0 + r*16 + lq) * STRH + kk + 2*lr;
                af[r][0] = *(const uint32_t*)(p);
                af[r][1] = *(const uint32_t*)(p + 8*STRH);
                af[r][2] = *(const uint32_t*)(p + 8);
                af[r][3] = *(const uint32_t*)(p + 8*STRH + 8);
            }
            #pragma unroll
            for (int c = 0; c < 4; c++) {
                const __half* p = sB + (wc0 + c*8 + lq) * STRH + kk + 2*lr;
                bf[c][0] = *(const uint32_t*)(p);
                bf[c][1] = *(const uint32_t*)(p + 8);
            }
            #pragma unroll
            for (int r = 0; r < 4; r++)
                #pragma unroll
                for (int c = 0; c < 4; c++)
                    mma16816(acc[r][c], af[r], bf[c]);
        }
        __syncthreads();
    }

    // epilogue
    #pragma unroll
    for (int r = 0; r < 4; r++) {
        int row = row0 + wr0 + r*16 + lq;
        #pragma unroll
        for (int c = 0; c < 4; c++) {
            int col = col0 + wc0 + c*8 + lr*2;
            float2 b2 = *reinterpret_cast<const float2*>(bias + col);
            float v0 = acc[r][c][0] + b2.x, v1 = acc[r][c][1] + b2.y;
            float v2 = acc[r][c][2] + b2.x, v3 = acc[r][c][3] + b2.y;
            if (ACT) {
                v0 = 1.f/(1.f + __expf(-v0)); v1 = 1.f/(1.f + __expf(-v1));
                v2 = 1.f/(1.f + __expf(-v2)); v3 = 1.f/(1.f + __expf(-v3));
            }
            if (MODE == 0) {
                *reinterpret_cast<float2*>(C + (size_t)row*ldc + col)     = make_float2(v0, v1);
                *reinterpret_cast<float2*>(C + (size_t)(row+8)*ldc + col) = make_float2(v2, v3);
            } else {
                if (col0 < DD) {  // q -> half (uniform per block)
                    __half2 h0 = __floats2half2_rn(v0, v1);
                    __half2 h1 = __floats2half2_rn(v2, v3);
                    *(uint32_t*)(g_qh + (size_t)row*DD + col)     = *(uint32_t*)&h0;
                    *(uint32_t*)(g_qh + (size_t)(row+8)*DD + col) = *(uint32_t*)&h1;
                } else {          // k,v -> fp32 compact
                    int cc = col - DD;
                    *reinterpret_cast<float2*>(g_kv + (size_t)row*(2*DD) + cc)     = make_float2(v0, v1);
                    *reinterpret_cast<float2*>(g_kv + (size_t)(row+8)*(2*DD) + cc) = make_float2(v2, v3);
                }
            }
        }
    }
}

// ---------------- field[bh][d][n] = v * ||k|| -------------------------------
__global__ __launch_bounds__(256)
void field_kernel() {
    const int bh = blockIdx.y;
    const int b  = bh >> 4, h = bh & 15;
    const int n0 = blockIdx.x * 32;
    __shared__ float s_kmag[32];
    __shared__ float s_t[64][33];
    const int tid = threadIdx.x, lane = tid & 31, warp = tid >> 5;
    #pragma unroll
    for (int i = 0; i < 4; i++) {
        int nl = warp*4 + i;
        const float* kp = g_kv + ((size_t)(b*NN + n0 + nl))*(2*DD) + h*HD;
        float2 kv = reinterpret_cast<const float2*>(kp)[lane];
        float ss = kv.x*kv.x + kv.y*kv.y;
        #pragma unroll
        for (int o = 16; o; o >>= 1) ss += __shfl_xor_sync(0xffffffff, ss, o);
        if (lane == 0) s_kmag[nl] = sqrtf(ss);
    }
    __syncthreads();
    for (int idx = tid; idx < 2048; idx += 256) {
        int nl = idx >> 6, d = idx & 63;
        float v = g_kv[((size_t)(b*NN + n0 + nl))*(2*DD) + DD + h*HD + d];
        s_t[d][nl] = v * s_kmag[nl];
    }
    __syncthreads();
    for (int idx = tid; idx < 2048; idx += 256) {
        int d = idx >> 5, nl = idx & 31;
        g_field[((size_t)bh*HD + d)*NN + n0 + nl] = s_t[d][nl];
    }
}

// ---------------- pyramid + sparse skips ------------------------------------
__global__ __launch_bounds__(256)
void pyramid_kernel() {
    const int r = blockIdx.x;               // bh*64 + d
    const int h = (r >> 6) & 15;
    const float* row_g = g_field + (size_t)r * NN;
    __shared__ float s_row[NN];
    __shared__ float s_acc[NN];
    const int tid = threadIdx.x;
    for (int i = tid; i < NN/4; i += 256)
        reinterpret_cast<float4*>(s_row)[i] = reinterpret_cast<const float4*>(row_g)[i];
    float g[NSCALES];
    #pragma unroll
    for (int j = 0; j < NSCALES; j++) g[j] = g_gains[j*HH + h];
    const float sw0 = g_sw[0], sw1 = g_sw[1];
    __syncthreads();
    for (int n = tid; n < NN; n += 256) {
        float acc = 0.f;
        #pragma unroll
        for (int j = 0; j < NSCALES; j++) {
            int d = 1 << j;
            float y = C3 * s_row[n];
            if (n >= d)     y += C2 * s_row[n - d];
            if (n >= 2*d)   y += C1 * s_row[n - 2*d];
            if (n >= 3*d)   y += C0 * s_row[n - 3*d];
            acc += g[j] * y;
        }
        s_acc[n] = acc;
    }
    __syncthreads();
    float* out_g = g_acc + (size_t)r * NN;
    for (int n = tid; n < NN; n += 256) {
        float v = s_acc[n];
        if (n >= 512)  v += sw0 * s_acc[n - 512];
        if (n >= 1024) v += sw1 * s_acc[n - 1024];
        out_g[n] = v;
    }
}

// ------- fused coupling + transpose-back + gate + half-convert --------------
// block: (n-tile of 16, batch b). smem: s[h][nl*64+d] with row stride 1040.
#define CGP 1040
#define CGSMEM (HH*CGP*4)   // 66560 bytes
__global__ __launch_bounds__(256)
void cg_kernel() {
    extern __shared__ float s[];
    __shared__ float sc[HH*HH];
    const int b  = blockIdx.y;
    const int n0 = blockIdx.x * 16;
    const int tid = threadIdx.x;
    if (tid < HH*HH) sc[tid] = g_coup[tid];
    // load: 1024 source rows (j,d), 16 floats each
    for (int idx = tid; idx < 4096; idx += 256) {
        int row = idx >> 2, c4 = idx & 3;
        int j = row >> 6, d = row & 63;
        float4 v = *reinterpret_cast<const float4*>(
            g_acc + ((size_t)(b*HH + j)*HD + d)*NN + n0 + c4*4);
        float* sp = s + j*CGP + d;
        sp[(c4*4+0)*64] = v.x; sp[(c4*4+1)*64] = v.y;
        sp[(c4*4+2)*64] = v.z; sp[(c4*4+3)*64] = v.w;
    }
    __syncthreads();
    #pragma unroll
    for (int t = 0; t < 4; t++) {
        int p  = tid + 256*t;       // nl*64 + d
        int d  = p & 63, nl = p >> 6;
        float in[HH];
        #pragma unroll
        for (int j = 0; j < HH; j++) in[j] = s[j*CGP + nl*64 + d];
        #pragma unroll
        for (int h = 0; h < HH; h++) {
            float o = 0.f;
            #pragma unroll
            for (int j = 0; j < HH; j++) o += sc[h*HH + j] * in[j];
            size_t addr = ((size_t)(b*NN + n0 + nl))*DD + h*HD + d;
            g_preh[addr] = __float2half_rn(o * g_gate[addr]);
        }
    }
}

// ---------------- launch ----------------------------------------------------
extern "C" void kernel_launch(void* const* d_in, const int* in_sizes, int n_in,
                              void* d_out, int out_size) {
    const float* x          = (const float*)d_in[0];
    const float* Wqkv       = (const float*)d_in[1];
    const float* bqkv       = (const float*)d_in[2];
    const float* Wout       = (const float*)d_in[3];
    const float* bout       = (const float*)d_in[4];
    const float* Wgate      = (const float*)d_in[5];
    const float* bgate      = (const float*)d_in[6];
    const float* scale_gain = (const float*)d_in[7];
    const float* skip_w     = (const float*)d_in[8];
    const float* coupling   = (const float*)d_in[9];
    float* out = (float*)d_out;

    __half *p_xh, *p_qh, *p_preh, *p_wqkvT, *p_wgateT, *p_woutT;
    float *p_gate;
    cudaGetSymbolAddress((void**)&p_xh,     g_xh);
    cudaGetSymbolAddress((void**)&p_qh,     g_qh);
    cudaGetSymbolAddress((void**)&p_preh,   g_preh);
    cudaGetSymbolAddress((void**)&p_wqkvT,  g_wqkvT);
    cudaGetSymbolAddress((void**)&p_wgateT, g_wgateT);
    cudaGetSymbolAddress((void**)&p_woutT,  g_woutT);
    cudaGetSymbolAddress((void**)&p_gate,   g_gate);

    cudaFuncSetAttribute(mma_gemm<0,1>, cudaFuncAttributeMaxDynamicSharedMemorySize, GSMEM);
    cudaFuncSetAttribute(mma_gemm<1,0>, cudaFuncAttributeMaxDynamicSharedMemorySize, GSMEM);
    cudaFuncSetAttribute(mma_gemm<0,0>, cudaFuncAttributeMaxDynamicSharedMemorySize, GSMEM);
    cudaFuncSetAttribute(cg_kernel,     cudaFuncAttributeMaxDynamicSharedMemorySize, CGSMEM);

    prep_kernel<<<1, 32>>>(scale_gain, skip_w, coupling);

    wtrans_kernel<<<dim3(N3D/32, DD/32), 256>>>(Wqkv,  p_wqkvT,  DD, N3D);
    wtrans_kernel<<<dim3(DD/32,  DD/32), 256>>>(Wgate, p_wgateT, DD, DD);
    wtrans_kernel<<<dim3(DD/32,  DD/32), 256>>>(Wout,  p_woutT,  DD, DD);
    tohalf_kernel<<<(MTOT*DD/4)/256, 256>>>(x, p_xh);

    // GEMM1: qkv = x @ Wqkv + bqkv  (split epilogue: q->half, k|v->fp32)
    mma_gemm<0,1><<<dim3(N3D/128, MTOT/128), 256, GSMEM>>>(
        p_xh, p_wqkvT, bqkv, nullptr, 0, DD);
    // GEMM2: gate = sigmoid(q @ Wgate + bgate)
    mma_gemm<1,0><<<dim3(DD/128, MTOT/128), 256, GSMEM>>>(
        p_qh, p_wgateT, bgate, p_gate, DD, DD);

    field_kernel  <<<dim3(NN/32, BB*HH), 256>>>();
    pyramid_kernel<<<BB*HH*HD, 256>>>();
    cg_kernel     <<<dim3(NN/16, BB), 256, CGSMEM>>>();

    // GEMM3: out = pre @ Wout + bout
    mma_gemm<0,0><<<dim3(DD/128, MTOT/128), 256, GSMEM>>>(
        p_preh, p_woutT, bout, out, DD, DD);
}